// round 15
// baseline (speedup 1.0000x reference)
#include <cuda_runtime.h>
#include <math.h>

// Problem constants: generated [2, 3, 96, 96]
#define B       2
#define NPIX    9216            // 96*96
#define TOTQ    (B * NPIX)      // 18432 queries
#define K       8               // NUM_CLUSTERS
#define NTHR    256

#define NBIN    256             // x-bins (t = -2x space)
#define TMIN    (-12.0f)
#define INVW    (256.0f / 24.0f)

#define SPL     24              // samples per lane (768 total, stratified)
#define SSTR    384             // stratum stride (24*384 = 9216)

#define SWARPS  8               // warps per CTA
#define SBLK    (TOTQ / SWARPS) // 2304 CTAs
#define QCAP    512             // survivor queue capacity per warp

// Device scratch (allocation-free rule: __device__ globals)
__device__ float4   g_sorted[B * NPIX];        // bin-sorted {-2x,-2y,-2z,|c|^2}
__device__ unsigned g_hist[B * NBIN];          // zero at load; re-zeroed by scan
__device__ unsigned g_binstart[B * (NBIN + 1)];
__device__ unsigned g_binpos[B * NBIN];
__device__ float    g_bsum[SBLK];
__device__ unsigned g_ticket;                  // zero-init; self-resets

// Order-preserving float -> unsigned map (total order asc) and inverse.
__device__ __forceinline__ unsigned mapf(float d) {
    int v = __float_as_int(d);
    return (unsigned)(v ^ ((v >> 31) | 0x80000000));
}
__device__ __forceinline__ float unmapf(unsigned u) {
    int s = (int)u >> 31;
    unsigned m = (~(unsigned)s) | 0x80000000u;
    return __int_as_float((int)(u ^ m));
}

__device__ __forceinline__ int bin_of(float t) {
    int bn = (int)floorf((t - TMIN) * INVW);
    return min(NBIN - 1, max(0, bn));
}

// CE inserts (constant indexing -> registers)
__device__ __forceinline__ void insert4u(unsigned (&t)[4], unsigned u) {
    #pragma unroll
    for (int k = 0; k < 4; k++) { unsigned lo = min(t[k], u); u = max(t[k], u); t[k] = lo; }
}
__device__ __forceinline__ void insert8u(unsigned (&t)[8], unsigned u) {
    #pragma unroll
    for (int k = 0; k < 8; k++) { unsigned lo = min(t[k], u); u = max(t[k], u); t[k] = lo; }
}
__device__ __forceinline__ void insert8f(float (&t)[8], float u) {
    #pragma unroll
    for (int k = 0; k < 8; k++) { float lo = fminf(t[k], u); u = fmaxf(t[k], u); t[k] = lo; }
}

// ---------------------------------------------------------------------------
// Kernel 1: per-batch histogram of t = -2x (smem hist, CTA-uniform batch)
// ---------------------------------------------------------------------------
__global__ void hist_kernel(const float* __restrict__ in) {
    __shared__ unsigned h[NBIN];
    int tid = threadIdx.x;
    for (int i = tid; i < NBIN; i += NTHR) h[i] = 0;
    __syncthreads();

    int idx = blockIdx.x * NTHR + tid;           // [0, TOTQ)
    int b = idx / NPIX;                          // uniform per CTA (9216/256=36)
    int i = idx - b * NPIX;
    float t = -2.0f * in[(size_t)b * 3 * NPIX + i];
    atomicAdd(&h[bin_of(t)], 1u);
    __syncthreads();

    for (int i2 = tid; i2 < NBIN; i2 += NTHR)
        if (h[i2]) atomicAdd(&g_hist[b * NBIN + i2], h[i2]);
}

// ---------------------------------------------------------------------------
// Kernel 2: exclusive prefix per batch -> binstart/binpos; zero hist for the
// next graph replay (invariant: hist is zero before every hist_kernel run).
// ---------------------------------------------------------------------------
__global__ void __launch_bounds__(NBIN)
scan_kernel() {
    __shared__ unsigned sv[NBIN];
    int tid = threadIdx.x;
    for (int b = 0; b < B; b++) {
        unsigned v = g_hist[b * NBIN + tid];
        sv[tid] = v;
        __syncthreads();
        for (int off = 1; off < NBIN; off <<= 1) {
            unsigned add = (tid >= off) ? sv[tid - off] : 0u;
            __syncthreads();
            sv[tid] += add;
            __syncthreads();
        }
        unsigned incl = sv[tid];
        unsigned excl = incl - v;
        g_binstart[b * (NBIN + 1) + tid] = excl;
        if (tid == NBIN - 1) g_binstart[b * (NBIN + 1) + NBIN] = incl;
        g_binpos[b * NBIN + tid] = excl;
        g_hist[b * NBIN + tid] = 0;
        __syncthreads();
    }
}

// ---------------------------------------------------------------------------
// Kernel 3: scatter candidates into bin-sorted order (order within bin free)
// ---------------------------------------------------------------------------
__global__ void scatter_kernel(const float* __restrict__ in) {
    int idx = blockIdx.x * NTHR + threadIdx.x;   // [0, TOTQ)
    int b = idx / NPIX;
    int i = idx - b * NPIX;
    const float* base = in + (size_t)b * 3 * NPIX;
    float x = base[i];
    float y = base[NPIX + i];
    float z = base[2 * NPIX + i];
    float s = x * x + y * y + z * z;
    float mx = -2.0f * x, my = -2.0f * y, mz = -2.0f * z;
    int bn = bin_of(mx);
    unsigned pos = atomicAdd(&g_binpos[b * NBIN + bn], 1u);
    g_sorted[b * NPIX + pos] = make_float4(mx, my, mz, s);
}

// ---------------------------------------------------------------------------
// Kernel 4 (fused, WARP-PER-QUERY):
//  A) threshold T from 768 stratified samples (lane top-2 + redux merge)
//  B) slab scan |t_c - t_q| <= 2r; survivors compacted by BALLOT (no atomics)
//  C) balanced top-8 (uint CE + REDUX.MIN merge); exact fallbacks throughout
// ---------------------------------------------------------------------------
__global__ void __launch_bounds__(NTHR)
scanselect_kernel(const float* __restrict__ in, float* __restrict__ out) {
    __shared__ float    squeue[SWARPS][QCAP];     // 16 KB
    __shared__ float    red[SWARPS];
    __shared__ float    red2[NTHR];
    __shared__ int      islast;

    int tid  = threadIdx.x;
    int lane = tid & 31;
    int wid  = tid >> 5;
    int q = blockIdx.x * SWARPS + wid;            // [0, TOTQ); batch-clean split
    int b = q / NPIX;
    int qi = q - b * NPIX;
    const float* base = in + (size_t)b * 3 * NPIX;
    float ax = base[qi], ay = base[NPIX + qi], az = base[2 * NPIX + qi];
    float q2 = fmaf(ax, ax, fmaf(ay, ay, az * az));
    float tq = -2.0f * ax;

    const float4* sb = g_sorted + b * NPIX;

    // ---- Phase A: threshold from stratified sample (L1-shared per CTA) ----
    float p1 = 3.0e30f, p2 = 3.0e30f, r1 = 3.0e30f, r2 = 3.0e30f;
    #pragma unroll 4
    for (int j = 0; j < SPL; j += 2) {
        float4 cv = sb[j * SSTR + lane];
        float d = fmaf(ax, cv.x, fmaf(ay, cv.y, fmaf(az, cv.z, cv.w)));
        float lo = fminf(p1, d), hi = fmaxf(p1, d);
        p1 = lo; p2 = fminf(p2, hi);
        float4 cw = sb[(j + 1) * SSTR + lane];
        float e = fmaf(ax, cw.x, fmaf(ay, cw.y, fmaf(az, cw.z, cw.w)));
        lo = fminf(r1, e); hi = fmaxf(r1, e);
        r1 = lo; r2 = fminf(r2, hi);
    }
    float m1 = fminf(p1, r1);
    float mm = fmaxf(p1, r1);
    float m2 = fminf(fminf(p2, r2), mm);
    unsigned v = mapf(m1), v2 = mapf(m2), vres = 0;
    #pragma unroll
    for (int k = 0; k < K; k++) {
        unsigned m = __reduce_min_sync(0xFFFFFFFFu, v);
        unsigned ball = __ballot_sync(0xFFFFFFFFu, v == m);
        int src = __ffs(ball) - 1;
        if (lane == src) { v = v2; v2 = 0xFFFFFFFFu; }
        vres = m;
    }
    float Tf = nextafterf(unmapf(vres), 3.4e38f);   // admit d == T downstream

    // ---- Phase B: slab scan + BALLOT-compacted survivor queue ----
    float rr = sqrtf(fmaxf(Tf + q2, 0.0f)) * 1.001f;   // d-space radius, inflated
    int lo_b = max(0, (int)floorf((tq - 2.0f * rr - TMIN) * INVW));
    int hi_b = min(NBIN - 1, (int)floorf((tq + 2.0f * rr - TMIN) * INVW));
    int s0 = (int)g_binstart[b * (NBIN + 1) + lo_b];
    int s1 = (int)g_binstart[b * (NBIN + 1) + hi_b + 1];

    unsigned cnt = 0;                      // warp-uniform register count
    unsigned lmask = (1u << lane) - 1u;    // lower-lane mask
    for (int bb = s0; bb < s1; bb += 32) {
        int ii = bb + lane;
        float d = 3.0e30f;
        if (ii < s1) {
            float4 cv = sb[ii];
            d = fmaf(ax, cv.x, fmaf(ay, cv.y, fmaf(az, cv.z, cv.w)));
        }
        bool surv = d < Tf;
        unsigned ball = __ballot_sync(0xFFFFFFFFu, surv);
        if (surv) {
            unsigned pos = cnt + __popc(ball & lmask);
            if (pos < QCAP) squeue[wid][pos] = d;
        }
        cnt += __popc(ball);
    }
    __syncwarp();

    // ---- Phase C: exact top-8 ----
    float ssum = 0.0f;
    if (cnt <= 128u) {
        // <=4 items per lane: 4-deep state, nothing can be dropped
        unsigned t[4] = {0xFFFFFFFFu, 0xFFFFFFFFu, 0xFFFFFFFFu, 0xFFFFFFFFu};
        for (unsigned bb = 0; bb < cnt; bb += 32) {
            unsigned ii = bb + lane;
            unsigned u = (ii < cnt) ? mapf(squeue[wid][ii]) : 0xFFFFFFFFu;
            insert4u(t, u);
        }
        #pragma unroll
        for (int k = 0; k < K; k++) {
            unsigned m = __reduce_min_sync(0xFFFFFFFFu, t[0]);
            unsigned ball = __ballot_sync(0xFFFFFFFFu, t[0] == m);
            int src = __ffs(ball) - 1;
            if (lane == src) { t[0] = t[1]; t[1] = t[2]; t[2] = t[3]; t[3] = 0xFFFFFFFFu; }
            if (k > 0) ssum += sqrtf(fmaxf(unmapf(m) + q2, 0.0f));   // k=0: self
        }
    } else if (cnt <= QCAP) {
        // lane-top-8 provably retains any global-top-8 member
        unsigned t[8];
        #pragma unroll
        for (int k = 0; k < 8; k++) t[k] = 0xFFFFFFFFu;
        for (unsigned bb = 0; bb < cnt; bb += 32) {
            unsigned ii = bb + lane;
            unsigned u = (ii < cnt) ? mapf(squeue[wid][ii]) : 0xFFFFFFFFu;
            insert8u(t, u);
        }
        #pragma unroll
        for (int k = 0; k < K; k++) {
            unsigned m = __reduce_min_sync(0xFFFFFFFFu, t[0]);
            unsigned ball = __ballot_sync(0xFFFFFFFFu, t[0] == m);
            int src = __ffs(ball) - 1;
            if (lane == src) {
                #pragma unroll
                for (int j = 0; j < 7; j++) t[j] = t[j + 1];
                t[7] = 0xFFFFFFFFu;
            }
            if (k > 0) ssum += sqrtf(fmaxf(unmapf(m) + q2, 0.0f));
        }
    } else {
        // overflow (~never): exact lane-strided slab rescan, float merge
        float t8[8];
        #pragma unroll
        for (int k = 0; k < 8; k++) t8[k] = 3.0e30f;
        for (int ii = s0 + lane; ii < s1; ii += 32) {
            float4 cv = sb[ii];
            float d = fmaf(ax, cv.x, fmaf(ay, cv.y, fmaf(az, cv.z, cv.w)));
            if (d < t8[7]) insert8f(t8, d);
        }
        #pragma unroll
        for (int k = 0; k < K; k++) {
            float vv = t8[0];
            float m = vv;
            #pragma unroll
            for (int off = 16; off > 0; off >>= 1)
                m = fminf(m, __shfl_xor_sync(0xFFFFFFFFu, m, off));
            unsigned ball = __ballot_sync(0xFFFFFFFFu, vv == m);
            int src = __ffs(ball) - 1;
            if (lane == src) {
                #pragma unroll
                for (int j = 0; j < 7; j++) t8[j] = t8[j + 1];
                t8[7] = 3.0e30f;
            }
            if (k > 0) ssum += sqrtf(fmaxf(m + q2, 0.0f));
        }
    }

    if (lane == 0) red[wid] = ssum;
    __syncthreads();

    if (tid == 0) {
        float bs = 0.0f;
        #pragma unroll
        for (int wv = 0; wv < SWARPS; wv++) bs += red[wv];
        g_bsum[blockIdx.x] = bs;
        __threadfence();
        unsigned r = atomicAdd(&g_ticket, 1u);
        islast = (r == (unsigned)(gridDim.x - 1));
    }
    __syncthreads();

    if (islast) {
        float vv = 0.0f;
        for (int i = tid; i < SBLK; i += NTHR) vv += __ldcg(&g_bsum[i]);
        red2[tid] = vv;
        __syncthreads();
        #pragma unroll
        for (int w = NTHR / 2; w > 0; w >>= 1) {
            if (tid < w) red2[tid] += red2[tid + w];
            __syncthreads();
        }
        if (tid == 0) {
            out[0] = -red2[0] / (float)(TOTQ * K);
            g_ticket = 0;    // reset for next graph replay
        }
    }
}

extern "C" void kernel_launch(void* const* d_in, const int* in_sizes, int n_in,
                              void* d_out, int out_size) {
    const float* in = (const float*)d_in[0];
    float* out = (float*)d_out;

    hist_kernel<<<TOTQ / NTHR, NTHR>>>(in);
    scan_kernel<<<1, NBIN>>>();
    scatter_kernel<<<TOTQ / NTHR, NTHR>>>(in);
    scanselect_kernel<<<SBLK, NTHR>>>(in, out);
}

// round 16
// speedup vs baseline: 1.2487x; 1.2487x over previous
#include <cuda_runtime.h>
#include <math.h>

// Problem constants: generated [2, 3, 96, 96]
#define B       2
#define NPIX    9216            // 96*96
#define TOTQ    (B * NPIX)      // 18432 queries
#define K       8               // NUM_CLUSTERS
#define NTHR    256

#define NBIN    256             // x-bins (t = -2x space)
#define TMIN    (-12.0f)
#define INVW    (256.0f / 24.0f)

#define SPL     32              // samples per lane (1024 total, stratified)
#define SSTR    288             // stratum stride (32*288 = 9216)

#define SWARPS  8               // warps per CTA
#define SBLK    (TOTQ / SWARPS) // 2304 CTAs
#define CAP     16              // per-lane survivor strip capacity

// Device scratch (allocation-free rule: __device__ globals)
__device__ float4   g_sorted[B * NPIX];        // bin-sorted {-2x,-2y,-2z,|c|^2}
__device__ unsigned g_hist[B * NBIN];          // zero at load; re-zeroed by scan
__device__ unsigned g_binstart[B * (NBIN + 1)];
__device__ unsigned g_binpos[B * NBIN];
__device__ float    g_bsum[SBLK];
__device__ unsigned g_ticket;                  // zero-init; self-resets

// Order-preserving float -> unsigned map (total order asc) and inverse.
__device__ __forceinline__ unsigned mapf(float d) {
    int v = __float_as_int(d);
    return (unsigned)(v ^ ((v >> 31) | 0x80000000));
}
__device__ __forceinline__ float unmapf(unsigned u) {
    int s = (int)u >> 31;
    unsigned m = (~(unsigned)s) | 0x80000000u;
    return __int_as_float((int)(u ^ m));
}

__device__ __forceinline__ int bin_of(float t) {
    int bn = (int)floorf((t - TMIN) * INVW);
    return min(NBIN - 1, max(0, bn));
}

// CE inserts (constant indexing -> registers)
__device__ __forceinline__ void insert8u(unsigned (&t)[8], unsigned u) {
    #pragma unroll
    for (int k = 0; k < 8; k++) { unsigned lo = min(t[k], u); u = max(t[k], u); t[k] = lo; }
}
__device__ __forceinline__ void insert8f(float (&t)[8], float u) {
    #pragma unroll
    for (int k = 0; k < 8; k++) { float lo = fminf(t[k], u); u = fmaxf(t[k], u); t[k] = lo; }
}

// ---------------------------------------------------------------------------
// Kernel 1: per-batch histogram of t = -2x (smem hist, CTA-uniform batch)
// ---------------------------------------------------------------------------
__global__ void hist_kernel(const float* __restrict__ in) {
    __shared__ unsigned h[NBIN];
    int tid = threadIdx.x;
    for (int i = tid; i < NBIN; i += NTHR) h[i] = 0;
    __syncthreads();

    int idx = blockIdx.x * NTHR + tid;           // [0, TOTQ)
    int b = idx / NPIX;                          // uniform per CTA (9216/256=36)
    int i = idx - b * NPIX;
    float t = -2.0f * in[(size_t)b * 3 * NPIX + i];
    atomicAdd(&h[bin_of(t)], 1u);
    __syncthreads();

    for (int i2 = tid; i2 < NBIN; i2 += NTHR)
        if (h[i2]) atomicAdd(&g_hist[b * NBIN + i2], h[i2]);
}

// ---------------------------------------------------------------------------
// Kernel 2: exclusive prefix per batch -> binstart/binpos; zero hist for the
// next graph replay (invariant: hist is zero before every hist_kernel run).
// ---------------------------------------------------------------------------
__global__ void __launch_bounds__(NBIN)
scan_kernel() {
    __shared__ unsigned sv[NBIN];
    int tid = threadIdx.x;
    for (int b = 0; b < B; b++) {
        unsigned v = g_hist[b * NBIN + tid];
        sv[tid] = v;
        __syncthreads();
        for (int off = 1; off < NBIN; off <<= 1) {
            unsigned add = (tid >= off) ? sv[tid - off] : 0u;
            __syncthreads();
            sv[tid] += add;
            __syncthreads();
        }
        unsigned incl = sv[tid];
        unsigned excl = incl - v;
        g_binstart[b * (NBIN + 1) + tid] = excl;
        if (tid == NBIN - 1) g_binstart[b * (NBIN + 1) + NBIN] = incl;
        g_binpos[b * NBIN + tid] = excl;
        g_hist[b * NBIN + tid] = 0;
        __syncthreads();
    }
}

// ---------------------------------------------------------------------------
// Kernel 3: scatter candidates into bin-sorted order (order within bin free)
// ---------------------------------------------------------------------------
__global__ void scatter_kernel(const float* __restrict__ in) {
    int idx = blockIdx.x * NTHR + threadIdx.x;   // [0, TOTQ)
    int b = idx / NPIX;
    int i = idx - b * NPIX;
    const float* base = in + (size_t)b * 3 * NPIX;
    float x = base[i];
    float y = base[NPIX + i];
    float z = base[2 * NPIX + i];
    float s = x * x + y * y + z * z;
    float mx = -2.0f * x, my = -2.0f * y, mz = -2.0f * z;
    int bn = bin_of(mx);
    unsigned pos = atomicAdd(&g_binpos[b * NBIN + bn], 1u);
    g_sorted[b * NPIX + pos] = make_float4(mx, my, mz, s);
}

// ---------------------------------------------------------------------------
// Kernel 4 (fused, WARP-PER-QUERY, queries enumerated in SORTED order so
// adjacent warps share L1-hot slabs):
//  A) threshold T from 1024 stratified samples (lane top-2 + redux merge)
//  B) slab scan: lane-private survivor strips, NO ballots/atomics, unroll 4
//  C) lane-local top-8 over own strip + REDUX.MIN merge; overflow -> exact
// ---------------------------------------------------------------------------
__global__ void __launch_bounds__(NTHR)
scanselect_kernel(float* __restrict__ out) {
    __shared__ float strip[SWARPS][CAP][32];      // 16 KB, conflict-free layout
    __shared__ float red[SWARPS];
    __shared__ float red2[NTHR];
    __shared__ int   islast;

    int tid  = threadIdx.x;
    int lane = tid & 31;
    int wid  = tid >> 5;
    int j = blockIdx.x * SWARPS + wid;            // sorted-order query index
    int b = j / NPIX;
    int jj = j - b * NPIX;

    const float4* sb = g_sorted + b * NPIX;
    float4 qv = sb[jj];                           // this query's own record
    float ax = -0.5f * qv.x;                      // exact (Â±0.5 scaling)
    float ay = -0.5f * qv.y;
    float az = -0.5f * qv.z;
    float q2 = qv.w;
    float tq = qv.x;                              // t = -2x

    // ---- Phase A: threshold from stratified sample (L1-shared) ----
    float p1 = 3.0e30f, p2 = 3.0e30f, r1 = 3.0e30f, r2 = 3.0e30f;
    #pragma unroll 4
    for (int s = 0; s < SPL; s += 2) {
        float4 cv = sb[s * SSTR + lane];
        float d = fmaf(ax, cv.x, fmaf(ay, cv.y, fmaf(az, cv.z, cv.w)));
        float lo = fminf(p1, d), hi = fmaxf(p1, d);
        p1 = lo; p2 = fminf(p2, hi);
        float4 cw = sb[(s + 1) * SSTR + lane];
        float e = fmaf(ax, cw.x, fmaf(ay, cw.y, fmaf(az, cw.z, cw.w)));
        lo = fminf(r1, e); hi = fmaxf(r1, e);
        r1 = lo; r2 = fminf(r2, hi);
    }
    float m1 = fminf(p1, r1);
    float mm = fmaxf(p1, r1);
    float m2 = fminf(fminf(p2, r2), mm);
    unsigned v = mapf(m1), v2 = mapf(m2), vres = 0;
    #pragma unroll
    for (int k = 0; k < K; k++) {
        unsigned m = __reduce_min_sync(0xFFFFFFFFu, v);
        unsigned ball = __ballot_sync(0xFFFFFFFFu, v == m);
        int src = __ffs(ball) - 1;
        if (lane == src) { v = v2; v2 = 0xFFFFFFFFu; }
        vres = m;
    }
    float Tf = nextafterf(unmapf(vres), 3.4e38f);   // admit d == T downstream

    // ---- Phase B: slab scan into lane-private strips (no warp sync) ----
    float rr = sqrtf(fmaxf(Tf + q2, 0.0f)) * 1.001f;   // distance-space radius
    int lo_b = max(0, (int)floorf((tq - 2.0f * rr - TMIN) * INVW));
    int hi_b = min(NBIN - 1, (int)floorf((tq + 2.0f * rr - TMIN) * INVW));
    int s0 = (int)g_binstart[b * (NBIN + 1) + lo_b];
    int s1 = (int)g_binstart[b * (NBIN + 1) + hi_b + 1];

    int cnt = 0;                                  // per-lane survivor count
    for (int bb = s0; bb < s1; bb += 128) {
        #pragma unroll
        for (int u = 0; u < 4; u++) {
            int ii = bb + u * 32 + lane;
            int iic = min(ii, s1 - 1);            // clamped, always in-bounds
            float4 cv = sb[iic];
            float d = fmaf(ax, cv.x, fmaf(ay, cv.y, fmaf(az, cv.z, cv.w)));
            bool surv = (d < Tf) && (ii < s1);
            int pos = min(cnt, CAP - 1);
            strip[wid][pos][lane] = d;            // unconditional; junk slots
            cnt += surv ? 1 : 0;                  // get overwritten
        }
    }

    unsigned ofl = __ballot_sync(0xFFFFFFFFu, cnt > CAP);
    float ssum = 0.0f;

    if (ofl == 0u) {
        // ---- Phase C: lane-local top-8 over own strip + REDUX merge ----
        unsigned t[8];
        #pragma unroll
        for (int k = 0; k < 8; k++) t[k] = 0xFFFFFFFFu;
        for (int c = 0; c < cnt; c++)
            insert8u(t, mapf(strip[wid][c][lane]));
        #pragma unroll
        for (int k = 0; k < K; k++) {
            unsigned m = __reduce_min_sync(0xFFFFFFFFu, t[0]);
            unsigned ball = __ballot_sync(0xFFFFFFFFu, t[0] == m);
            int src = __ffs(ball) - 1;
            if (lane == src) {
                #pragma unroll
                for (int c = 0; c < 7; c++) t[c] = t[c + 1];
                t[7] = 0xFFFFFFFFu;
            }
            if (k > 0) ssum += sqrtf(fmaxf(unmapf(m) + q2, 0.0f));   // k=0: self
        }
    } else {
        // overflow (~never): exact lane-strided slab rescan, float merge
        float t8[8];
        #pragma unroll
        for (int k = 0; k < 8; k++) t8[k] = 3.0e30f;
        for (int ii = s0 + lane; ii < s1; ii += 32) {
            float4 cv = sb[ii];
            float d = fmaf(ax, cv.x, fmaf(ay, cv.y, fmaf(az, cv.z, cv.w)));
            if (d < t8[7]) insert8f(t8, d);
        }
        #pragma unroll
        for (int k = 0; k < K; k++) {
            float vv = t8[0];
            float m = vv;
            #pragma unroll
            for (int off = 16; off > 0; off >>= 1)
                m = fminf(m, __shfl_xor_sync(0xFFFFFFFFu, m, off));
            unsigned ball = __ballot_sync(0xFFFFFFFFu, vv == m);
            int src = __ffs(ball) - 1;
            if (lane == src) {
                #pragma unroll
                for (int c = 0; c < 7; c++) t8[c] = t8[c + 1];
                t8[7] = 3.0e30f;
            }
            if (k > 0) ssum += sqrtf(fmaxf(m + q2, 0.0f));
        }
    }

    if (lane == 0) red[wid] = ssum;
    __syncthreads();

    if (tid == 0) {
        float bs = 0.0f;
        #pragma unroll
        for (int wv = 0; wv < SWARPS; wv++) bs += red[wv];
        g_bsum[blockIdx.x] = bs;
        __threadfence();
        unsigned r = atomicAdd(&g_ticket, 1u);
        islast = (r == (unsigned)(gridDim.x - 1));
    }
    __syncthreads();

    if (islast) {
        float vv = 0.0f;
        for (int i = tid; i < SBLK; i += NTHR) vv += __ldcg(&g_bsum[i]);
        red2[tid] = vv;
        __syncthreads();
        #pragma unroll
        for (int w = NTHR / 2; w > 0; w >>= 1) {
            if (tid < w) red2[tid] += red2[tid + w];
            __syncthreads();
        }
        if (tid == 0) {
            out[0] = -red2[0] / (float)(TOTQ * K);
            g_ticket = 0;    // reset for next graph replay
        }
    }
}

extern "C" void kernel_launch(void* const* d_in, const int* in_sizes, int n_in,
                              void* d_out, int out_size) {
    const float* in = (const float*)d_in[0];
    float* out = (float*)d_out;

    hist_kernel<<<TOTQ / NTHR, NTHR>>>(in);
    scan_kernel<<<1, NBIN>>>();
    scatter_kernel<<<TOTQ / NTHR, NTHR>>>(in);
    scanselect_kernel<<<SBLK, NTHR>>>(out);
}

// round 17
// speedup vs baseline: 1.2869x; 1.0306x over previous
#include <cuda_runtime.h>
#include <math.h>

// Problem constants: generated [2, 3, 96, 96]
#define B       2
#define NPIX    9216            // 96*96
#define TOTQ    (B * NPIX)      // 18432 queries
#define K       8               // NUM_CLUSTERS
#define NTHR    256

#define NBX     64              // x-bins (t = -2x space)
#define NBY     64              // y-bins (t = -2y space)
#define NB2     (NBX * NBY)     // 4096 bins per batch
#define TMIN    (-12.0f)
#define INVW    (64.0f / 24.0f) // bins per unit t (width 0.375)

#define SPL     32              // samples per lane (1024 total, stratified)
#define SSTR    288             // stratum stride (32*288 = 9216)

#define SWARPS  8               // warps per CTA
#define SBLK    (TOTQ / SWARPS) // 2304 CTAs
#define CAP     16              // per-lane survivor strip capacity

// Device scratch (allocation-free rule: __device__ globals)
__device__ float4   g_sorted[B * NPIX];          // bin-sorted {-2x,-2y,-2z,|c|^2}
__device__ unsigned g_hist[B * NB2];             // zero at load; re-zeroed by scan
__device__ unsigned g_binstart[B * (NB2 + 1)];
__device__ unsigned g_binpos[B * NB2];
__device__ float    g_bsum[SBLK];
__device__ unsigned g_ticket;                    // zero-init; self-resets

// Order-preserving float -> unsigned map (total order asc) and inverse.
__device__ __forceinline__ unsigned mapf(float d) {
    int v = __float_as_int(d);
    return (unsigned)(v ^ ((v >> 31) | 0x80000000));
}
__device__ __forceinline__ float unmapf(unsigned u) {
    int s = (int)u >> 31;
    unsigned m = (~(unsigned)s) | 0x80000000u;
    return __int_as_float((int)(u ^ m));
}

__device__ __forceinline__ int bin1(float t) {     // 1D bin with clamp
    int bn = (int)floorf((t - TMIN) * INVW);
    return min(63, max(0, bn));
}

// CE inserts (constant indexing -> registers)
__device__ __forceinline__ void insert8u(unsigned (&t)[8], unsigned u) {
    #pragma unroll
    for (int k = 0; k < 8; k++) { unsigned lo = min(t[k], u); u = max(t[k], u); t[k] = lo; }
}
__device__ __forceinline__ void insert8f(float (&t)[8], float u) {
    #pragma unroll
    for (int k = 0; k < 8; k++) { float lo = fminf(t[k], u); u = fmaxf(t[k], u); t[k] = lo; }
}

// ---------------------------------------------------------------------------
// Kernel 1: per-batch 2D histogram over (tx, ty) bins (smem hist)
// ---------------------------------------------------------------------------
__global__ void hist_kernel(const float* __restrict__ in) {
    __shared__ unsigned h[NB2];                    // 16 KB
    int tid = threadIdx.x;
    #pragma unroll
    for (int i = tid; i < NB2; i += NTHR) h[i] = 0;
    __syncthreads();

    int idx = blockIdx.x * NTHR + tid;             // [0, TOTQ)
    int b = idx / NPIX;                            // uniform per CTA (36 CTAs/batch)
    int i = idx - b * NPIX;
    const float* base = in + (size_t)b * 3 * NPIX;
    float tx = -2.0f * base[i];
    float ty = -2.0f * base[NPIX + i];
    atomicAdd(&h[bin1(ty) * NBX + bin1(tx)], 1u);
    __syncthreads();

    for (int i2 = tid; i2 < NB2; i2 += NTHR)
        if (h[i2]) atomicAdd(&g_hist[b * NB2 + i2], h[i2]);
}

// ---------------------------------------------------------------------------
// Kernel 2: exclusive prefix per batch over 4096 bins (16 bins/thread +
// 256-partial smem scan); zeroes hist for the next graph replay.
// ---------------------------------------------------------------------------
__global__ void __launch_bounds__(NTHR)
scan_kernel() {
    __shared__ unsigned sv[NTHR];
    int tid = threadIdx.x;
    for (int b = 0; b < B; b++) {
        unsigned v[16];
        unsigned seg = 0;
        #pragma unroll
        for (int k = 0; k < 16; k++) {
            v[k] = g_hist[b * NB2 + tid * 16 + k];
            seg += v[k];
        }
        sv[tid] = seg;
        __syncthreads();
        for (int off = 1; off < NTHR; off <<= 1) {
            unsigned add = (tid >= off) ? sv[tid - off] : 0u;
            __syncthreads();
            sv[tid] += add;
            __syncthreads();
        }
        unsigned run = sv[tid] - seg;              // exclusive thread prefix
        #pragma unroll
        for (int k = 0; k < 16; k++) {
            g_binstart[b * (NB2 + 1) + tid * 16 + k] = run;
            g_binpos[b * NB2 + tid * 16 + k] = run;
            run += v[k];
            g_hist[b * NB2 + tid * 16 + k] = 0;
        }
        if (tid == NTHR - 1) g_binstart[b * (NB2 + 1) + NB2] = NPIX;
        __syncthreads();
    }
}

// ---------------------------------------------------------------------------
// Kernel 3: scatter candidates into 2D-bin-sorted order
// ---------------------------------------------------------------------------
__global__ void scatter_kernel(const float* __restrict__ in) {
    int idx = blockIdx.x * NTHR + threadIdx.x;     // [0, TOTQ)
    int b = idx / NPIX;
    int i = idx - b * NPIX;
    const float* base = in + (size_t)b * 3 * NPIX;
    float x = base[i];
    float y = base[NPIX + i];
    float z = base[2 * NPIX + i];
    float s = x * x + y * y + z * z;
    float mx = -2.0f * x, my = -2.0f * y, mz = -2.0f * z;
    int bn = bin1(my) * NBX + bin1(mx);
    unsigned pos = atomicAdd(&g_binpos[b * NB2 + bn], 1u);
    g_sorted[b * NPIX + pos] = make_float4(mx, my, mz, s);
}

// ---------------------------------------------------------------------------
// Kernel 4 (fused, WARP-PER-QUERY, sorted-order queries -> L1-hot rows):
//  A) threshold T from 1024 stratified samples (lane top-2 + redux merge)
//  B) 2D window scan: y-rows of x-runs, lane-private strips, no ballots
//  C) lane-local top-8 + REDUX.MIN merge; overflow -> exact row rescan
// ---------------------------------------------------------------------------
__global__ void __launch_bounds__(NTHR)
scanselect_kernel(float* __restrict__ out) {
    __shared__ float strip[SWARPS][CAP][32];       // 16 KB, conflict-free
    __shared__ float red[SWARPS];
    __shared__ float red2[NTHR];
    __shared__ int   islast;

    int tid  = threadIdx.x;
    int lane = tid & 31;
    int wid  = tid >> 5;
    int j = blockIdx.x * SWARPS + wid;             // sorted-order query index
    int b = j / NPIX;
    int jj = j - b * NPIX;

    const float4* sb = g_sorted + b * NPIX;
    const unsigned* bs = g_binstart + b * (NB2 + 1);
    float4 qv = sb[jj];                            // this query's own record
    float ax = -0.5f * qv.x;                       // exact (x0.5 scaling)
    float ay = -0.5f * qv.y;
    float az = -0.5f * qv.z;
    float q2 = qv.w;
    float tqx = qv.x, tqy = qv.y;

    // ---- Phase A: threshold from stratified sample (L1-shared) ----
    float p1 = 3.0e30f, p2 = 3.0e30f, r1 = 3.0e30f, r2 = 3.0e30f;
    #pragma unroll 4
    for (int s = 0; s < SPL; s += 2) {
        float4 cv = sb[s * SSTR + lane];
        float d = fmaf(ax, cv.x, fmaf(ay, cv.y, fmaf(az, cv.z, cv.w)));
        float lo = fminf(p1, d), hi = fmaxf(p1, d);
        p1 = lo; p2 = fminf(p2, hi);
        float4 cw = sb[(s + 1) * SSTR + lane];
        float e = fmaf(ax, cw.x, fmaf(ay, cw.y, fmaf(az, cw.z, cw.w)));
        lo = fminf(r1, e); hi = fmaxf(r1, e);
        r1 = lo; r2 = fminf(r2, hi);
    }
    float m1 = fminf(p1, r1);
    float mm = fmaxf(p1, r1);
    float m2 = fminf(fminf(p2, r2), mm);
    unsigned v = mapf(m1), v2 = mapf(m2), vres = 0;
    #pragma unroll
    for (int k = 0; k < K; k++) {
        unsigned m = __reduce_min_sync(0xFFFFFFFFu, v);
        unsigned ball = __ballot_sync(0xFFFFFFFFu, v == m);
        int src = __ffs(ball) - 1;
        if (lane == src) { v = v2; v2 = 0xFFFFFFFFu; }
        vres = m;
    }
    float Tf = nextafterf(unmapf(vres), 3.4e38f);  // admit d == T downstream

    // ---- Phase B: 2D window scan into lane-private strips ----
    float rr = sqrtf(fmaxf(Tf + q2, 0.0f)) * 1.001f;  // distance-space radius
    float w2 = 2.0f * rr;                             // t-space half-width
    int bxlo = max(0,  (int)floorf((tqx - w2 - TMIN) * INVW));
    int bxhi = min(63, (int)floorf((tqx + w2 - TMIN) * INVW));
    int bylo = max(0,  (int)floorf((tqy - w2 - TMIN) * INVW));
    int byhi = min(63, (int)floorf((tqy + w2 - TMIN) * INVW));

    int cnt = 0;                                   // per-lane survivor count
    for (int by = bylo; by <= byhi; by++) {
        int rowb = by * NBX;
        int s0 = (int)bs[rowb + bxlo];
        int s1 = (int)bs[rowb + bxhi + 1];
        for (int bb = s0; bb < s1; bb += 32) {
            int ii = bb + lane;
            int iic = min(ii, s1 - 1);             // clamped, always in-bounds
            float4 cv = sb[iic];
            float d = fmaf(ax, cv.x, fmaf(ay, cv.y, fmaf(az, cv.z, cv.w)));
            bool surv = (d < Tf) && (ii < s1);
            int pos = min(cnt, CAP - 1);
            strip[wid][pos][lane] = d;             // unconditional; junk slots
            cnt += surv ? 1 : 0;                   // get overwritten
        }
    }

    // cnt >= CAP: a later junk store may have clobbered slot CAP-1 -> exact path
    unsigned ofl = __ballot_sync(0xFFFFFFFFu, cnt >= CAP);
    float ssum = 0.0f;

    if (ofl == 0u) {
        // ---- Phase C: lane-local top-8 over own strip + REDUX merge ----
        unsigned t[8];
        #pragma unroll
        for (int k = 0; k < 8; k++) t[k] = 0xFFFFFFFFu;
        for (int c = 0; c < cnt; c++)
            insert8u(t, mapf(strip[wid][c][lane]));
        #pragma unroll
        for (int k = 0; k < K; k++) {
            unsigned m = __reduce_min_sync(0xFFFFFFFFu, t[0]);
            unsigned ball = __ballot_sync(0xFFFFFFFFu, t[0] == m);
            int src = __ffs(ball) - 1;
            if (lane == src) {
                #pragma unroll
                for (int c = 0; c < 7; c++) t[c] = t[c + 1];
                t[7] = 0xFFFFFFFFu;
            }
            if (k > 0) ssum += sqrtf(fmaxf(unmapf(m) + q2, 0.0f));  // k=0: self
        }
    } else {
        // overflow (~never): exact lane-strided row rescan, float merge
        float t8[8];
        #pragma unroll
        for (int k = 0; k < 8; k++) t8[k] = 3.0e30f;
        for (int by = bylo; by <= byhi; by++) {
            int rowb = by * NBX;
            int s0 = (int)bs[rowb + bxlo];
            int s1 = (int)bs[rowb + bxhi + 1];
            for (int ii = s0 + lane; ii < s1; ii += 32) {
                float4 cv = sb[ii];
                float d = fmaf(ax, cv.x, fmaf(ay, cv.y, fmaf(az, cv.z, cv.w)));
                if (d < t8[7]) insert8f(t8, d);
            }
        }
        #pragma unroll
        for (int k = 0; k < K; k++) {
            float vv = t8[0];
            float m = vv;
            #pragma unroll
            for (int off = 16; off > 0; off >>= 1)
                m = fminf(m, __shfl_xor_sync(0xFFFFFFFFu, m, off));
            unsigned ball = __ballot_sync(0xFFFFFFFFu, vv == m);
            int src = __ffs(ball) - 1;
            if (lane == src) {
                #pragma unroll
                for (int c = 0; c < 7; c++) t8[c] = t8[c + 1];
                t8[7] = 3.0e30f;
            }
            if (k > 0) ssum += sqrtf(fmaxf(m + q2, 0.0f));
        }
    }

    if (lane == 0) red[wid] = ssum;
    __syncthreads();

    if (tid == 0) {
        float bsm = 0.0f;
        #pragma unroll
        for (int wv = 0; wv < SWARPS; wv++) bsm += red[wv];
        g_bsum[blockIdx.x] = bsm;
        __threadfence();
        unsigned r = atomicAdd(&g_ticket, 1u);
        islast = (r == (unsigned)(gridDim.x - 1));
    }
    __syncthreads();

    if (islast) {
        float vv = 0.0f;
        for (int i = tid; i < SBLK; i += NTHR) vv += __ldcg(&g_bsum[i]);
        red2[tid] = vv;
        __syncthreads();
        #pragma unroll
        for (int w = NTHR / 2; w > 0; w >>= 1) {
            if (tid < w) red2[tid] += red2[tid + w];
            __syncthreads();
        }
        if (tid == 0) {
            out[0] = -red2[0] / (float)(TOTQ * K);
            g_ticket = 0;    // reset for next graph replay
        }
    }
}

extern "C" void kernel_launch(void* const* d_in, const int* in_sizes, int n_in,
                              void* d_out, int out_size) {
    const float* in = (const float*)d_in[0];
    float* out = (float*)d_out;

    hist_kernel<<<TOTQ / NTHR, NTHR>>>(in);
    scan_kernel<<<1, NTHR>>>();
    scatter_kernel<<<TOTQ / NTHR, NTHR>>>(in);
    scanselect_kernel<<<SBLK, NTHR>>>(out);
}